// round 2
// baseline (speedup 1.0000x reference)
#include <cuda_runtime.h>

// DSSIM — fused separable-Gaussian SSIM + mean (4-stream formulation)
// d_in[0]=image1 [32,3,512,512] f32, d_in[1]=image2, d_in[2]=gauss_kernel [3,1,11,11] f32
// out[0] = mean((1 - ssim_map)/2)

#define IMH 512
#define IMW 512
#define TW 32
#define TH 32
#define INW 42
#define INH 42
#define INP 43              // sIn pitch (float2 units)
#define NBLK (16*16*96)     // 24576 partials
#define NRED1 96            // stage-1 reduce blocks: 96*256 = 24576
#define C1F 1.0e-4f
#define C2F 9.0e-4f

typedef unsigned long long u64;

static __device__ __forceinline__ u64 pk2(float lo, float hi) {
    u64 r; asm("mov.b64 %0, {%1,%2};" : "=l"(r) : "f"(lo), "f"(hi)); return r;
}
static __device__ __forceinline__ void up2(u64 v, float& lo, float& hi) {
    asm("mov.b64 {%0,%1}, %2;" : "=f"(lo), "=f"(hi) : "l"(v));
}
static __device__ __forceinline__ u64 fma2(u64 a, u64 b, u64 c) {
    u64 d; asm("fma.rn.f32x2 %0, %1, %2, %3;" : "=l"(d) : "l"(a), "l"(b), "l"(c)); return d;
}

__device__ float  g_part[NBLK];
__device__ double g_part2[NRED1];

__global__ __launch_bounds__(256) void dssim_main(
    const float* __restrict__ im1,
    const float* __restrict__ im2,
    const float* __restrict__ kern)
{
    __shared__ float2 sIn[INH * INP];   // (x, y) input pairs with halo
    __shared__ float4 sH[INH * TW];     // H-blurred (mu1, mu2, x2+y2, xy)
    __shared__ float  sW[6];
    __shared__ float  sWarp[8];

    const int tid = threadIdx.x;
    const int x0 = blockIdx.x * TW;
    const int y0 = blockIdx.y * TH;
    const size_t pbase = (size_t)blockIdx.z * (IMH * IMW);

    // 1D weights = row sums of normalized 2D kernel; symmetric, keep 6
    if (tid < 6) {
        float s = 0.f;
        #pragma unroll
        for (int j = 0; j < 11; ++j) s += kern[tid * 11 + j];
        sW[tid] = s;
    }

    // Stage input tile + halo (zero pad = conv SAME-zero semantics)
    for (int i = tid; i < INH * INW; i += 256) {
        int r = i / INW;
        int c = i - r * INW;
        int gy = y0 + r - 5;
        int gx = x0 + c - 5;
        float v1 = 0.f, v2 = 0.f;
        if ((unsigned)gy < IMH && (unsigned)gx < IMW) {
            size_t o = pbase + (size_t)gy * IMW + gx;
            v1 = im1[o];
            v2 = im2[o];
        }
        sIn[r * INP + c] = make_float2(v1, v2);
    }
    __syncthreads();

    u64 ww[6];
    #pragma unroll
    for (int i = 0; i < 6; ++i) { float w = sW[i]; ww[i] = pk2(w, w); }

    // ---- Horizontal pass: 42 rows x 4 col-groups of 8 = 168 threads ----
    if (tid < 168) {
        const int r  = tid >> 2;
        const int cx = (tid & 3) << 3;
        u64 aA[8], aB[8];
        #pragma unroll
        for (int j = 0; j < 8; ++j) { aA[j] = 0ull; aB[j] = 0ull; }
        const float2* rp = &sIn[r * INP + cx];
        #pragma unroll
        for (int k = 0; k < 18; ++k) {
            float2 v = rp[k];
            float s  = fmaf(v.x, v.x, v.y * v.y);
            float xy = v.x * v.y;
            u64 A = pk2(v.x, v.y);
            u64 B = pk2(s, xy);
            #pragma unroll
            for (int j = 0; j < 8; ++j) {
                const int t = k - j;
                if (t >= 0 && t <= 10) {
                    const int wi = (t < 6) ? t : 10 - t;
                    aA[j] = fma2(ww[wi], A, aA[j]);
                    aB[j] = fma2(ww[wi], B, aB[j]);
                }
            }
        }
        #pragma unroll
        for (int j = 0; j < 8; ++j) {
            float m1, m2, s, xy;
            up2(aA[j], m1, m2);
            up2(aB[j], s, xy);
            sH[r * TW + cx + j] = make_float4(m1, m2, s, xy);
        }
    }
    __syncthreads();

    // ---- Vertical pass + SSIM: 8 warps x 4 rows, one column per lane ----
    const int x  = tid & 31;
    const int ys = (tid >> 5) << 2;
    u64 aA[4], aB[4];
    #pragma unroll
    for (int j = 0; j < 4; ++j) { aA[j] = 0ull; aB[j] = 0ull; }
    #pragma unroll
    for (int k = 0; k < 14; ++k) {
        float4 h = sH[(ys + k) * TW + x];
        u64 M = pk2(h.x, h.y);
        u64 B = pk2(h.z, h.w);
        #pragma unroll
        for (int j = 0; j < 4; ++j) {
            const int t = k - j;
            if (t >= 0 && t <= 10) {
                const int wi = (t < 6) ? t : 10 - t;
                aA[j] = fma2(ww[wi], M, aA[j]);
                aB[j] = fma2(ww[wi], B, aB[j]);
            }
        }
    }

    float local = 0.f;
    #pragma unroll
    for (int j = 0; j < 4; ++j) {
        float mu1, mu2, S, bxy;
        up2(aA[j], mu1, mu2);
        up2(aB[j], S, bxy);
        float mu12 = mu1 * mu2;
        float A2   = fmaf(mu1, mu1, mu2 * mu2);   // mu1^2 + mu2^2
        float s12  = bxy - mu12;                  // sigma12
        float sS   = S - A2;                      // sigma1^2 + sigma2^2
        float num = fmaf(2.f, mu12, C1F) * fmaf(2.f, s12, C2F);
        float den = (A2 + C1F) * (sS + C2F);
        local += (1.f - __fdividef(num, den)) * 0.5f;
    }

    #pragma unroll
    for (int o = 16; o; o >>= 1) local += __shfl_xor_sync(0xffffffffu, local, o);
    if ((tid & 31) == 0) sWarp[tid >> 5] = local;
    __syncthreads();
    if (tid == 0) {
        float bs = 0.f;
        #pragma unroll
        for (int i = 0; i < 8; ++i) bs += sWarp[i];
        g_part[((int)blockIdx.z * 16 + (int)blockIdx.y) * 16 + (int)blockIdx.x] = bs;
    }
}

__global__ __launch_bounds__(256) void dssim_reduce1()
{
    __shared__ double sd[256];
    const int t = threadIdx.x;
    sd[t] = (double)g_part[blockIdx.x * 256 + t];
    __syncthreads();
    #pragma unroll
    for (int o = 128; o; o >>= 1) {
        if (t < o) sd[t] += sd[t + o];
        __syncthreads();
    }
    if (t == 0) g_part2[blockIdx.x] = sd[0];
}

__global__ __launch_bounds__(128) void dssim_reduce2(float* __restrict__ out)
{
    __shared__ double sd[128];
    const int t = threadIdx.x;
    sd[t] = (t < NRED1) ? g_part2[t] : 0.0;
    __syncthreads();
    #pragma unroll
    for (int o = 64; o; o >>= 1) {
        if (t < o) sd[t] += sd[t + o];
        __syncthreads();
    }
    if (t == 0) out[0] = (float)(sd[0] / (double)(32.0 * 3.0 * 512.0 * 512.0));
}

extern "C" void kernel_launch(void* const* d_in, const int* in_sizes, int n_in,
                              void* d_out, int out_size)
{
    const float* im1  = (const float*)d_in[0];
    const float* im2  = (const float*)d_in[1];
    const float* kern = (const float*)d_in[2];
    float* out = (float*)d_out;

    dim3 grid(IMW / TW, IMH / TH, 96);   // 16 x 16 x 96
    dssim_main<<<grid, 256>>>(im1, im2, kern);
    dssim_reduce1<<<NRED1, 256>>>();
    dssim_reduce2<<<1, 128>>>(out);
}

// round 3
// speedup vs baseline: 1.0130x; 1.0130x over previous
#include <cuda_runtime.h>

// DSSIM — fused separable-Gaussian SSIM + mean, 4-stream f32x2 formulation.
// Round 3: bank-conflict-free smem layouts (sH pitch 33), vectorized staging,
// 32x64 tiles.

#define IMH 512
#define IMW 512
#define TW 32
#define TH 64
#define SROWS 74            // TH + 10 staged rows
#define SCOLS 48            // staged cols: [x0-8, x0+40), 16B-aligned quads
#define INP 50              // sIn pitch in float2 units (400B, 16B-aligned rows)
#define HP 33               // sH pitch in float4 units (odd => conflict-free STS)
#define GX 16
#define GY 8
#define NBLK (GX*GY*96)     // 12288
#define NRED1 48            // 48*256 = 12288
#define C1F 1.0e-4f
#define C2F 9.0e-4f

typedef unsigned long long u64;

static __device__ __forceinline__ u64 pk2(float lo, float hi) {
    u64 r; asm("mov.b64 %0, {%1,%2};" : "=l"(r) : "f"(lo), "f"(hi)); return r;
}
static __device__ __forceinline__ void up2(u64 v, float& lo, float& hi) {
    asm("mov.b64 {%0,%1}, %2;" : "=f"(lo), "=f"(hi) : "l"(v));
}
static __device__ __forceinline__ u64 fma2(u64 a, u64 b, u64 c) {
    u64 d; asm("fma.rn.f32x2 %0, %1, %2, %3;" : "=l"(d) : "l"(a), "l"(b), "l"(c)); return d;
}

__device__ float  g_part[NBLK];
__device__ double g_part2[NRED1];

__global__ __launch_bounds__(256, 3) void dssim_main(
    const float* __restrict__ im1,
    const float* __restrict__ im2,
    const float* __restrict__ kern)
{
    __shared__ float2 sIn[SROWS * INP];   // interleaved (x, y), pitch 50
    __shared__ float4 sH[SROWS * HP];     // H-blurred (mu1, mu2, x2+y2, xy), pitch 33
    __shared__ float  sW[6];
    __shared__ float  sWarp[8];

    const int tid = threadIdx.x;
    const int x0 = blockIdx.x * TW;
    const int y0 = blockIdx.y * TH;
    const size_t pbase = (size_t)blockIdx.z * (IMH * IMW);

    if (tid < 6) {
        float s = 0.f;
        #pragma unroll
        for (int j = 0; j < 11; ++j) s += kern[tid * 11 + j];
        sW[tid] = s;
    }

    // ---- Staging: 74 rows x 12 aligned float4-quads (x0-8 .. x0+39) ----
    for (int i = tid; i < SROWS * 12; i += 256) {
        const int r = i / 12;
        const int q = i - r * 12;
        const int gy = y0 + r - 5;
        const int gx = x0 + (q << 2) - 8;
        float4 a = make_float4(0.f, 0.f, 0.f, 0.f);
        float4 b = a;
        if ((unsigned)gy < IMH && gx >= 0 && gx <= IMW - 4) {
            const size_t o = pbase + (size_t)gy * IMW + gx;
            a = *(const float4*)(im1 + o);
            b = *(const float4*)(im2 + o);
        }
        float4* dst = (float4*)&sIn[r * INP + (q << 2)];
        dst[0] = make_float4(a.x, b.x, a.y, b.y);
        dst[1] = make_float4(a.z, b.z, a.w, b.w);
    }
    __syncthreads();

    u64 ww[6];
    #pragma unroll
    for (int i = 0; i < 6; ++i) { float w = sW[i]; ww[i] = pk2(w, w); }

    // ---- Horizontal pass: 74 rows x 4 groups-of-8 = 296 tasks ----
    for (int g = tid; g < SROWS * 4; g += 256) {
        const int r  = g >> 2;
        const int cx = (g & 3) << 3;
        u64 aA[8], aB[8];
        #pragma unroll
        for (int j = 0; j < 8; ++j) { aA[j] = 0ull; aB[j] = 0ull; }
        // output col cj tap t reads local col cj + t + 3  (gx = x0 + c - 8)
        const float2* rp = &sIn[r * INP + cx + 3];
        #pragma unroll
        for (int k = 0; k < 18; ++k) {
            float2 v = rp[k];
            float s  = fmaf(v.x, v.x, v.y * v.y);
            float xy = v.x * v.y;
            u64 A = pk2(v.x, v.y);
            u64 B = pk2(s, xy);
            #pragma unroll
            for (int j = 0; j < 8; ++j) {
                const int t = k - j;
                if (t >= 0 && t <= 10) {
                    const int wi = (t < 6) ? t : 10 - t;
                    aA[j] = fma2(ww[wi], A, aA[j]);
                    aB[j] = fma2(ww[wi], B, aB[j]);
                }
            }
        }
        #pragma unroll
        for (int j = 0; j < 8; ++j) {
            float m1, m2, s, xy;
            up2(aA[j], m1, m2);
            up2(aB[j], s, xy);
            sH[r * HP + cx + j] = make_float4(m1, m2, s, xy);
        }
    }
    __syncthreads();

    // ---- Vertical pass + SSIM: 32 cols x 8 row-groups-of-8 = 256 tasks ----
    const int x  = tid & 31;
    const int ys = (tid >> 5) << 3;
    u64 aA[8], aB[8];
    #pragma unroll
    for (int j = 0; j < 8; ++j) { aA[j] = 0ull; aB[j] = 0ull; }
    #pragma unroll
    for (int k = 0; k < 18; ++k) {
        float4 h = sH[(ys + k) * HP + x];
        u64 M = pk2(h.x, h.y);
        u64 B = pk2(h.z, h.w);
        #pragma unroll
        for (int j = 0; j < 8; ++j) {
            const int t = k - j;
            if (t >= 0 && t <= 10) {
                const int wi = (t < 6) ? t : 10 - t;
                aA[j] = fma2(ww[wi], M, aA[j]);
                aB[j] = fma2(ww[wi], B, aB[j]);
            }
        }
    }

    float local = 0.f;
    #pragma unroll
    for (int j = 0; j < 8; ++j) {
        float mu1, mu2, S, bxy;
        up2(aA[j], mu1, mu2);
        up2(aB[j], S, bxy);
        float mu12 = mu1 * mu2;
        float A2   = fmaf(mu1, mu1, mu2 * mu2);
        float s12  = bxy - mu12;
        float sS   = S - A2;
        float num = fmaf(2.f, mu12, C1F) * fmaf(2.f, s12, C2F);
        float den = (A2 + C1F) * (sS + C2F);
        local += (1.f - __fdividef(num, den)) * 0.5f;
    }

    #pragma unroll
    for (int o = 16; o; o >>= 1) local += __shfl_xor_sync(0xffffffffu, local, o);
    if ((tid & 31) == 0) sWarp[tid >> 5] = local;
    __syncthreads();
    if (tid == 0) {
        float bs = 0.f;
        #pragma unroll
        for (int i = 0; i < 8; ++i) bs += sWarp[i];
        g_part[((int)blockIdx.z * GY + (int)blockIdx.y) * GX + (int)blockIdx.x] = bs;
    }
}

__global__ __launch_bounds__(256) void dssim_reduce1()
{
    __shared__ double sd[256];
    const int t = threadIdx.x;
    sd[t] = (double)g_part[blockIdx.x * 256 + t];
    __syncthreads();
    #pragma unroll
    for (int o = 128; o; o >>= 1) {
        if (t < o) sd[t] += sd[t + o];
        __syncthreads();
    }
    if (t == 0) g_part2[blockIdx.x] = sd[0];
}

__global__ __launch_bounds__(64) void dssim_reduce2(float* __restrict__ out)
{
    __shared__ double sd[64];
    const int t = threadIdx.x;
    sd[t] = (t < NRED1) ? g_part2[t] : 0.0;
    __syncthreads();
    #pragma unroll
    for (int o = 32; o; o >>= 1) {
        if (t < o) sd[t] += sd[t + o];
        __syncthreads();
    }
    if (t == 0) out[0] = (float)(sd[0] / (double)(32.0 * 3.0 * 512.0 * 512.0));
}

extern "C" void kernel_launch(void* const* d_in, const int* in_sizes, int n_in,
                              void* d_out, int out_size)
{
    const float* im1  = (const float*)d_in[0];
    const float* im2  = (const float*)d_in[1];
    const float* kern = (const float*)d_in[2];
    float* out = (float*)d_out;

    dim3 grid(GX, GY, 96);   // 16 x 8 x 96 tiles of 32x64
    dssim_main<<<grid, 256>>>(im1, im2, kern);
    dssim_reduce1<<<NRED1, 256>>>();
    dssim_reduce2<<<1, 64>>>(out);
}

// round 4
// speedup vs baseline: 1.6177x; 1.5969x over previous
#include <cuda_runtime.h>

// DSSIM — fused separable-Gaussian SSIM + mean, 4-stream f32x2 formulation.
// Round 4: H-pass loads via LDS.128 (2 taps per load), even-bank-group verified.

#define IMH 512
#define IMW 512
#define TW 32
#define TH 64
#define SROWS 74            // TH + 10 staged rows
#define INP 50              // sIn pitch in float2 units (400B = 25*16B)
#define HP 33               // sH pitch in float4 units
#define GX 16
#define GY 8
#define NBLK (GX*GY*96)     // 12288
#define NRED1 48            // 48*256 = 12288
#define C1F 1.0e-4f
#define C2F 9.0e-4f

typedef unsigned long long u64;

static __device__ __forceinline__ u64 pk2(float lo, float hi) {
    u64 r; asm("mov.b64 %0, {%1,%2};" : "=l"(r) : "f"(lo), "f"(hi)); return r;
}
static __device__ __forceinline__ void up2(u64 v, float& lo, float& hi) {
    asm("mov.b64 {%0,%1}, %2;" : "=f"(lo), "=f"(hi) : "l"(v));
}
static __device__ __forceinline__ u64 fma2(u64 a, u64 b, u64 c) {
    u64 d; asm("fma.rn.f32x2 %0, %1, %2, %3;" : "=l"(d) : "l"(a), "l"(b), "l"(c)); return d;
}

__device__ float  g_part[NBLK];
__device__ double g_part2[NRED1];

// Accumulate one input pixel (vx,vy) at tap position k into 8 streaming outputs.
// k is compile-time after unrolling => invalid (k-j) pairs are statically elided.
#define ACC(kk, vx, vy) do {                                            \
    const float _s  = fmaf((vx), (vx), (vy) * (vy));                    \
    const float _xy = (vx) * (vy);                                      \
    const u64 _A = pk2((vx), (vy));                                     \
    const u64 _B = pk2(_s, _xy);                                        \
    _Pragma("unroll")                                                   \
    for (int j = 0; j < 8; ++j) {                                       \
        const int t = (kk) - j;                                         \
        if (t >= 0 && t <= 10) {                                        \
            const int wi = (t < 6) ? t : 10 - t;                        \
            aA[j] = fma2(ww[wi], _A, aA[j]);                            \
            aB[j] = fma2(ww[wi], _B, aB[j]);                            \
        }                                                               \
    }                                                                   \
} while (0)

__global__ __launch_bounds__(256, 3) void dssim_main(
    const float* __restrict__ im1,
    const float* __restrict__ im2,
    const float* __restrict__ kern)
{
    __shared__ float2 sIn[SROWS * INP];   // interleaved (x, y), pitch 50 (16B-aligned rows)
    __shared__ float4 sH[SROWS * HP];     // H-blurred (mu1, mu2, x2+y2, xy), pitch 33
    __shared__ float  sW[6];
    __shared__ float  sWarp[8];

    const int tid = threadIdx.x;
    const int x0 = blockIdx.x * TW;
    const int y0 = blockIdx.y * TH;
    const size_t pbase = (size_t)blockIdx.z * (IMH * IMW);

    if (tid < 6) {
        float s = 0.f;
        #pragma unroll
        for (int j = 0; j < 11; ++j) s += kern[tid * 11 + j];
        sW[tid] = s;
    }

    // ---- Staging: 74 rows x 12 aligned float4-quads covering [x0-8, x0+40) ----
    for (int i = tid; i < SROWS * 12; i += 256) {
        const int r = i / 12;
        const int q = i - r * 12;
        const int gy = y0 + r - 5;
        const int gx = x0 + (q << 2) - 8;
        float4 a = make_float4(0.f, 0.f, 0.f, 0.f);
        float4 b = a;
        if ((unsigned)gy < IMH && gx >= 0 && gx <= IMW - 4) {
            const size_t o = pbase + (size_t)gy * IMW + gx;
            a = *(const float4*)(im1 + o);
            b = *(const float4*)(im2 + o);
        }
        float4* dst = (float4*)&sIn[r * INP + (q << 2)];
        dst[0] = make_float4(a.x, b.x, a.y, b.y);
        dst[1] = make_float4(a.z, b.z, a.w, b.w);
    }
    __syncthreads();

    u64 ww[6];
    #pragma unroll
    for (int i = 0; i < 6; ++i) { float w = sW[i]; ww[i] = pk2(w, w); }

    // ---- Horizontal pass: 74 rows x 4 groups-of-8; loads as LDS.128 ----
    // Output col (cx+j) tap t reads local px cx+3+k, k=j+t in [0,17].
    // Load q covers px pair (cx+2+2q, cx+3+2q): px0 -> k=2q-1, px1 -> k=2q.
    for (int g = tid; g < SROWS * 4; g += 256) {
        const int r  = g >> 2;
        const int cx = (g & 3) << 3;
        u64 aA[8], aB[8];
        #pragma unroll
        for (int j = 0; j < 8; ++j) { aA[j] = 0ull; aB[j] = 0ull; }

        const float4* rp4 = (const float4*)&sIn[r * INP];
        const int qb = (cx >> 1) + 1;          // float4 index of px pair (cx+2, cx+3)
        #pragma unroll
        for (int q = 0; q < 10; ++q) {
            const float4 L = rp4[qb + q];      // (x1,x2) of px e, then px e+1
            if (q > 0) ACC(2 * q - 1, L.x, L.y);
            if (q < 9) ACC(2 * q,     L.z, L.w);
        }

        #pragma unroll
        for (int j = 0; j < 8; ++j) {
            float m1, m2, s, xy;
            up2(aA[j], m1, m2);
            up2(aB[j], s, xy);
            sH[r * HP + cx + j] = make_float4(m1, m2, s, xy);
        }
    }
    __syncthreads();

    // ---- Vertical pass + SSIM: 32 cols x 8 row-groups-of-8 ----
    const int x  = tid & 31;
    const int ys = (tid >> 5) << 3;
    u64 aA[8], aB[8];
    #pragma unroll
    for (int j = 0; j < 8; ++j) { aA[j] = 0ull; aB[j] = 0ull; }
    #pragma unroll
    for (int k = 0; k < 18; ++k) {
        float4 h = sH[(ys + k) * HP + x];
        u64 M = pk2(h.x, h.y);
        u64 B = pk2(h.z, h.w);
        #pragma unroll
        for (int j = 0; j < 8; ++j) {
            const int t = k - j;
            if (t >= 0 && t <= 10) {
                const int wi = (t < 6) ? t : 10 - t;
                aA[j] = fma2(ww[wi], M, aA[j]);
                aB[j] = fma2(ww[wi], B, aB[j]);
            }
        }
    }

    float local = 0.f;
    #pragma unroll
    for (int j = 0; j < 8; ++j) {
        float mu1, mu2, S, bxy;
        up2(aA[j], mu1, mu2);
        up2(aB[j], S, bxy);
        float mu12 = mu1 * mu2;
        float A2   = fmaf(mu1, mu1, mu2 * mu2);
        float s12  = bxy - mu12;
        float sS   = S - A2;
        float num = fmaf(2.f, mu12, C1F) * fmaf(2.f, s12, C2F);
        float den = (A2 + C1F) * (sS + C2F);
        local += (1.f - __fdividef(num, den)) * 0.5f;
    }

    #pragma unroll
    for (int o = 16; o; o >>= 1) local += __shfl_xor_sync(0xffffffffu, local, o);
    if ((tid & 31) == 0) sWarp[tid >> 5] = local;
    __syncthreads();
    if (tid == 0) {
        float bs = 0.f;
        #pragma unroll
        for (int i = 0; i < 8; ++i) bs += sWarp[i];
        g_part[((int)blockIdx.z * GY + (int)blockIdx.y) * GX + (int)blockIdx.x] = bs;
    }
}

__global__ __launch_bounds__(256) void dssim_reduce1()
{
    __shared__ double sd[256];
    const int t = threadIdx.x;
    sd[t] = (double)g_part[blockIdx.x * 256 + t];
    __syncthreads();
    #pragma unroll
    for (int o = 128; o; o >>= 1) {
        if (t < o) sd[t] += sd[t + o];
        __syncthreads();
    }
    if (t == 0) g_part2[blockIdx.x] = sd[0];
}

__global__ __launch_bounds__(64) void dssim_reduce2(float* __restrict__ out)
{
    __shared__ double sd[64];
    const int t = threadIdx.x;
    sd[t] = (t < NRED1) ? g_part2[t] : 0.0;
    __syncthreads();
    #pragma unroll
    for (int o = 32; o; o >>= 1) {
        if (t < o) sd[t] += sd[t + o];
        __syncthreads();
    }
    if (t == 0) out[0] = (float)(sd[0] / (double)(32.0 * 3.0 * 512.0 * 512.0));
}

extern "C" void kernel_launch(void* const* d_in, const int* in_sizes, int n_in,
                              void* d_out, int out_size)
{
    const float* im1  = (const float*)d_in[0];
    const float* im2  = (const float*)d_in[1];
    const float* kern = (const float*)d_in[2];
    float* out = (float*)d_out;

    dim3 grid(GX, GY, 96);   // 16 x 8 x 96 tiles of 32x64
    dssim_main<<<grid, 256>>>(im1, im2, kern);
    dssim_reduce1<<<NRED1, 256>>>();
    dssim_reduce2<<<1, 64>>>(out);
}